// round 13
// baseline (speedup 1.0000x reference)
#include <cuda_runtime.h>
#include <math.h>

#define Nn 50000
#define Ee 800000
#define Pp 800000

typedef unsigned long long u64;

// ---------------- scratch (device globals; no allocations allowed) ----------
__device__ float g_xw [Nn * 128];
__device__ float g_as [Nn * 4];
__device__ float g_ad [Nn * 4];
__device__ float g_h  [Nn * 128];
__device__ float g_xw2[Nn * 128];
__device__ float g_as2[Nn];
__device__ float g_ad2[Nn];
__device__ float g_z  [Nn * 128];
__device__ float g_u  [Nn * 128];
__device__ float g_v  [Nn * 128];
// CSR scratch
__device__ int g_deg[Nn];
__device__ int g_off[Nn + 1];
__device__ int g_cur[Nn];
__device__ int g_blk[64];
__device__ int g_src[Ee];

// ---------------- helpers ----------------------------------------------------
__device__ __forceinline__ float lrelu(float x) { return x > 0.f ? x : 0.2f * x; }
__device__ __forceinline__ float elu1(float x)  { return x > 0.f ? x : __expf(x) - 1.f; }

__device__ __forceinline__ u64 pack2(float lo, float hi) {
    u64 r;
    asm("mov.b64 %0, {%1, %2};" : "=l"(r)
        : "r"(__float_as_uint(lo)), "r"(__float_as_uint(hi)));
    return r;
}
__device__ __forceinline__ u64 ffma2(u64 a, u64 b, u64 c) {
    u64 d;
    asm("fma.rn.f32x2 %0, %1, %2, %3;" : "=l"(d) : "l"(a), "l"(b), "l"(c));
    return d;
}
__device__ __forceinline__ void unpack2(u64 v, float& lo, float& hi) {
    unsigned int a, b;
    asm("mov.b64 {%0, %1}, %2;" : "=r"(a), "=r"(b) : "l"(v));
    lo = __uint_as_float(a); hi = __uint_as_float(b);
}

// ---------------- CSR build --------------------------------------------------
__global__ void k_zero() {
    int i = blockIdx.x * blockDim.x + threadIdx.x;
    if (i < Nn) g_deg[i] = 0;
}

__global__ void k_count(const int* __restrict__ ei) {
    int e = blockIdx.x * blockDim.x + threadIdx.x;
    if (e < Ee) atomicAdd(&g_deg[ei[Ee + e]], 1);
}

__global__ void __launch_bounds__(1024) k_scan1() {
    __shared__ int wsum[32];
    int tid = threadIdx.x, lane = tid & 31, w = tid >> 5;
    int i = blockIdx.x * 1024 + tid;
    int v = (i < Nn) ? g_deg[i] : 0;
    int x = v;
#pragma unroll
    for (int off = 1; off < 32; off <<= 1) {
        int t = __shfl_up_sync(0xffffffffu, x, off);
        if (lane >= off) x += t;
    }
    if (lane == 31) wsum[w] = x;
    __syncthreads();
    if (w == 0) {
        int s = wsum[lane];
        int y = s;
#pragma unroll
        for (int off = 1; off < 32; off <<= 1) {
            int t = __shfl_up_sync(0xffffffffu, y, off);
            if (lane >= off) y += t;
        }
        wsum[lane] = y - s;
    }
    __syncthreads();
    int excl = (x - v) + wsum[w];
    if (i < Nn) g_off[i] = excl;
    if (tid == 1023) g_blk[blockIdx.x] = excl + v;
}

__global__ void k_scan2(int nblk) {
    int lane = threadIdx.x;
    int carry = 0;
    for (int c = 0; c < 2; c++) {
        int i = c * 32 + lane;
        int v = (i < nblk) ? g_blk[i] : 0;
        int x = v;
#pragma unroll
        for (int off = 1; off < 32; off <<= 1) {
            int t = __shfl_up_sync(0xffffffffu, x, off);
            if (lane >= off) x += t;
        }
        if (i < nblk) g_blk[i] = carry + x - v;
        carry += __shfl_sync(0xffffffffu, x, 31);
    }
    if (lane == 0) g_off[Nn] = Ee;
}

__global__ void k_scan3() {
    int i = blockIdx.x * blockDim.x + threadIdx.x;
    if (i >= Nn) return;
    int o = g_off[i] + g_blk[i >> 10];
    g_off[i] = o;
    g_cur[i] = o;
}

__global__ void k_fill(const int* __restrict__ ei) {
    int e = blockIdx.x * blockDim.x + threadIdx.x;
    if (e >= Ee) return;
    int s = ei[e], d = ei[Ee + e];
    int pos = atomicAdd(&g_cur[d], 1);
    g_src[pos] = s;
}

// ---------------- SGEMM: C[M,128] = A[M,128] @ B[128,128] (+bias) -----------
// R10 version (measured 46.4us, fma=45.6%): scalar A smem + pack2(a,a) MOVs.
// ALPHA: also emit alpha_s/alpha_d dots (per HEADS) from registers in epilogue.
template <int HEADS, bool ALPHA>
__global__ void __launch_bounds__(256) k_sgemm(const float* __restrict__ A,
                                               const float* __restrict__ B,
                                               const float* __restrict__ bias,
                                               float* __restrict__ C, int M,
                                               const float* __restrict__ aSrc,
                                               const float* __restrict__ aDst,
                                               float* __restrict__ oS,
                                               float* __restrict__ oD) {
    __shared__ float As[16][64];
    __shared__ float Bs[16][128];
    int tid = threadIdx.x;
    int tx = tid & 31, ty = tid >> 5;
    int m0 = blockIdx.x * 64;
    u64 acc[8][2];
#pragma unroll
    for (int i = 0; i < 8; i++) { acc[i][0] = 0ull; acc[i][1] = 0ull; }

    for (int kk = 0; kk < 128; kk += 16) {
        {
            int m = tid >> 2;
            int kq = tid & 3;
            float4 v = make_float4(0.f, 0.f, 0.f, 0.f);
            if (m0 + m < M)
                v = *(const float4*)(A + (size_t)(m0 + m) * 128 + kk + kq * 4);
            As[kq * 4 + 0][m] = v.x; As[kq * 4 + 1][m] = v.y;
            As[kq * 4 + 2][m] = v.z; As[kq * 4 + 3][m] = v.w;
        }
#pragma unroll
        for (int r = 0; r < 2; r++) {
            int idx = tid + r * 256;
            int k = idx >> 5, c4 = idx & 31;
            *(float4*)&Bs[k][c4 * 4] =
                *(const float4*)(B + (size_t)(kk + k) * 128 + c4 * 4);
        }
        __syncthreads();
#pragma unroll
        for (int k = 0; k < 16; k++) {
            float4 b = *(float4*)&Bs[k][tx * 4];
            u64 b01 = pack2(b.x, b.y), b23 = pack2(b.z, b.w);
#pragma unroll
            for (int i = 0; i < 8; i++) {
                float a = As[k][ty * 8 + i];
                u64 aa = pack2(a, a);
                acc[i][0] = ffma2(aa, b01, acc[i][0]);
                acc[i][1] = ffma2(aa, b23, acc[i][1]);
            }
        }
        __syncthreads();
    }
    float4 bb = make_float4(0.f, 0.f, 0.f, 0.f);
    if (bias) bb = *(const float4*)(bias + tx * 4);
    float4 sv = make_float4(0.f, 0.f, 0.f, 0.f);
    float4 dv = make_float4(0.f, 0.f, 0.f, 0.f);
    if (ALPHA) {
        sv = *(const float4*)(aSrc + tx * 4);
        dv = *(const float4*)(aDst + tx * 4);
    }
#pragma unroll
    for (int i = 0; i < 8; i++) {
        int m = m0 + ty * 8 + i;
        if (m < M) {
            float4 o;
            unpack2(acc[i][0], o.x, o.y);
            unpack2(acc[i][1], o.z, o.w);
            float4 w;
            w.x = o.x + bb.x; w.y = o.y + bb.y;
            w.z = o.z + bb.z; w.w = o.w + bb.w;
            *(float4*)(C + (size_t)m * 128 + tx * 4) = w;
            if (ALPHA) {
                float ps = o.x * sv.x + o.y * sv.y + o.z * sv.z + o.w * sv.w;
                float pd = o.x * dv.x + o.y * dv.y + o.z * dv.z + o.w * dv.w;
                if (HEADS == 4) {
#pragma unroll
                    for (int off = 4; off; off >>= 1) {
                        ps += __shfl_down_sync(0xffffffffu, ps, off, 8);
                        pd += __shfl_down_sync(0xffffffffu, pd, off, 8);
                    }
                    if ((tx & 7) == 0) {
                        oS[m * 4 + (tx >> 3)] = ps;
                        oD[m * 4 + (tx >> 3)] = pd;
                    }
                } else {
#pragma unroll
                    for (int off = 16; off; off >>= 1) {
                        ps += __shfl_down_sync(0xffffffffu, ps, off);
                        pd += __shfl_down_sync(0xffffffffu, pd, off);
                    }
                    if (tx == 0) { oS[m] = ps; oD[m] = pd; }
                }
            }
        }
    }
}

// ---------------- gather-based softmax aggregation (CSR) ---------------------
__global__ void k_agg1(const float* __restrict__ b1) {
    int t = blockIdx.x * blockDim.x + threadIdx.x;
    int node = t >> 5, lane = t & 31;
    if (node >= Nn) return;
    int h = lane >> 3;
    float adh = g_ad[node * 4 + h];
    float ex = __expf(lrelu(g_as[node * 4 + h] + adh));
    const float4* xw4 = (const float4*)g_xw;
    float4 v = xw4[(size_t)node * 32 + lane];
    float4 acc; acc.x = ex * v.x; acc.y = ex * v.y; acc.z = ex * v.z; acc.w = ex * v.w;
    float den = ex;
    int e = g_off[node], e1 = g_off[node + 1];
    for (; e + 2 <= e1; e += 2) {
        int s0 = g_src[e], s1 = g_src[e + 1];
        float l0 = g_as[s0 * 4 + h], l1 = g_as[s1 * 4 + h];
        float4 v0 = xw4[(size_t)s0 * 32 + lane];
        float4 v1 = xw4[(size_t)s1 * 32 + lane];
        float x0 = __expf(lrelu(l0 + adh)), x1 = __expf(lrelu(l1 + adh));
        acc.x += x0 * v0.x + x1 * v1.x; acc.y += x0 * v0.y + x1 * v1.y;
        acc.z += x0 * v0.z + x1 * v1.z; acc.w += x0 * v0.w + x1 * v1.w;
        den += x0 + x1;
    }
    if (e < e1) {
        int s0 = g_src[e];
        float x0 = __expf(lrelu(g_as[s0 * 4 + h] + adh));
        float4 v0 = xw4[(size_t)s0 * 32 + lane];
        acc.x += x0 * v0.x; acc.y += x0 * v0.y;
        acc.z += x0 * v0.z; acc.w += x0 * v0.w;
        den += x0;
    }
    float inv = 1.f / den;
    float4 b = ((const float4*)b1)[lane];
    float4 o;
    o.x = elu1(acc.x * inv + b.x); o.y = elu1(acc.y * inv + b.y);
    o.z = elu1(acc.z * inv + b.z); o.w = elu1(acc.w * inv + b.w);
    ((float4*)g_h)[(size_t)node * 32 + lane] = o;
}

__global__ void k_agg2(const float* __restrict__ b2) {
    int t = blockIdx.x * blockDim.x + threadIdx.x;
    int node = t >> 5, lane = t & 31;
    if (node >= Nn) return;
    float adh = g_ad2[node];
    float ex = __expf(lrelu(g_as2[node] + adh));
    const float4* xw4 = (const float4*)g_xw2;
    float4 v = xw4[(size_t)node * 32 + lane];
    float4 acc; acc.x = ex * v.x; acc.y = ex * v.y; acc.z = ex * v.z; acc.w = ex * v.w;
    float den = ex;
    int e = g_off[node], e1 = g_off[node + 1];
    for (; e + 2 <= e1; e += 2) {
        int s0 = g_src[e], s1 = g_src[e + 1];
        float l0 = g_as2[s0], l1 = g_as2[s1];
        float4 v0 = xw4[(size_t)s0 * 32 + lane];
        float4 v1 = xw4[(size_t)s1 * 32 + lane];
        float x0 = __expf(lrelu(l0 + adh)), x1 = __expf(lrelu(l1 + adh));
        acc.x += x0 * v0.x + x1 * v1.x; acc.y += x0 * v0.y + x1 * v1.y;
        acc.z += x0 * v0.z + x1 * v1.z; acc.w += x0 * v0.w + x1 * v1.w;
        den += x0 + x1;
    }
    if (e < e1) {
        int s0 = g_src[e];
        float x0 = __expf(lrelu(g_as2[s0] + adh));
        float4 v0 = xw4[(size_t)s0 * 32 + lane];
        acc.x += x0 * v0.x; acc.y += x0 * v0.y;
        acc.z += x0 * v0.z; acc.w += x0 * v0.w;
        den += x0;
    }
    float inv = 1.f / den;
    float4 b = ((const float4*)b2)[lane];
    float4 o;
    o.x = acc.x * inv + b.x; o.y = acc.y * inv + b.y;
    o.z = acc.z * inv + b.z; o.w = acc.w * inv + b.w;
    ((float4*)g_z)[(size_t)node * 32 + lane] = o;
}

// ---------------- edge-pair MLP: persistent register-tiled GEMM --------------
// MT=64 pairs per tile; weights staged in smem ONCE per block (persistent).
// Column-pair packing (R4/R6 config). MLP_BLOCKS = 148*3 for perfect balance.
#define MT 64
#define TS_STRIDE 132
#define NTILES (Pp / MT)
#define MLP_BLOCKS 444
#define SMEM_MLP (MT * TS_STRIDE * 4 + 128 * 32 * 8)

__global__ void __launch_bounds__(256) k_mlp(const int* __restrict__ ep,
                                             const float* __restrict__ mw2,
                                             const float* __restrict__ mb2,
                                             const float* __restrict__ mw3,
                                             const float* __restrict__ mb3,
                                             float* __restrict__ out) {
    extern __shared__ char smem[];
    float* Ts = (float*)smem;                       // [MT][TS_STRIDE]
    u64* w2p = (u64*)(smem + MT * TS_STRIDE * 4);   // [128][32] col pairs

    int tid = threadIdx.x;
    int tx = tid & 31, ty = tid >> 5;

    // stage packed weights once: w2p[k*32+c] = {mw2[k][c], mw2[k][c+32]}
    for (int e = tid; e < 128 * 32; e += 256) {
        int k = e >> 5, c = e & 31;
        w2p[e] = pack2(mw2[k * 64 + c], mw2[k * 64 + c + 32]);
    }
    u64 binit = pack2(__ldg(mb2 + tx), __ldg(mb2 + tx + 32));
    float w30 = __ldg(mw3 + tx), w31 = __ldg(mw3 + tx + 32);
    float mb3v = __ldg(mb3);
    int pair = tid >> 2, q = tid & 3;
    const float4* Ts4 = (const float4*)Ts;  // row stride = 33 float4

    for (int tile = blockIdx.x; tile < NTILES; tile += gridDim.x) {
        int P0 = tile * MT;
        __syncthreads();  // previous tile's readers done
        {   // gather + relu: 4 threads per pair, 8 float4 each
            int i = ep[P0 + pair], j = ep[Pp + P0 + pair];
            const float4* ur = (const float4*)g_u + (size_t)i * 32 + q * 8;
            const float4* vr = (const float4*)g_v + (size_t)j * 32 + q * 8;
            float4* dst = (float4*)(Ts + pair * TS_STRIDE) + q * 8;
#pragma unroll
            for (int r = 0; r < 8; r++) {
                float4 a = ur[r], b = vr[r], t;
                t.x = fmaxf(a.x + b.x, 0.f); t.y = fmaxf(a.y + b.y, 0.f);
                t.z = fmaxf(a.z + b.z, 0.f); t.w = fmaxf(a.w + b.w, 0.f);
                dst[r] = t;
            }
        }
        __syncthreads();

        u64 acc[8];
#pragma unroll
        for (int i = 0; i < 8; i++) acc[i] = binit;

#pragma unroll 2
        for (int kq = 0; kq < 32; kq++) {
            u64 b0 = w2p[(kq * 4 + 0) * 32 + tx];
            u64 b1 = w2p[(kq * 4 + 1) * 32 + tx];
            u64 b2 = w2p[(kq * 4 + 2) * 32 + tx];
            u64 b3 = w2p[(kq * 4 + 3) * 32 + tx];
#pragma unroll
            for (int i = 0; i < 8; i++) {
                float4 a = Ts4[(ty * 8 + i) * 33 + kq];
                acc[i] = ffma2(pack2(a.x, a.x), b0, acc[i]);
                acc[i] = ffma2(pack2(a.y, a.y), b1, acc[i]);
                acc[i] = ffma2(pack2(a.z, a.z), b2, acc[i]);
                acc[i] = ffma2(pack2(a.w, a.w), b3, acc[i]);
            }
        }

#pragma unroll
        for (int i = 0; i < 8; i++) {
            float o0, o1; unpack2(acc[i], o0, o1);
            o0 = fmaxf(o0, 0.f); o1 = fmaxf(o1, 0.f);
            float pv = o0 * w30 + o1 * w31;
#pragma unroll
            for (int off = 16; off; off >>= 1)
                pv += __shfl_down_sync(0xffffffffu, pv, off);
            if (tx == 0)
                out[P0 + ty * 8 + i] = 1.f / (1.f + __expf(-(pv + mb3v)));
        }
    }
}

// ---------------- launch ------------------------------------------------------
extern "C" void kernel_launch(void* const* d_in, const int* in_sizes, int n_in,
                              void* d_out, int out_size) {
    const float* x   = (const float*)d_in[0];
    const int*   ei  = (const int*)  d_in[1];
    const int*   ep  = (const int*)  d_in[2];
    const float* W1  = (const float*)d_in[3];
    const float* as1 = (const float*)d_in[4];
    const float* ad1 = (const float*)d_in[5];
    const float* b1  = (const float*)d_in[6];
    const float* W2  = (const float*)d_in[7];
    const float* as2 = (const float*)d_in[8];
    const float* ad2 = (const float*)d_in[9];
    const float* b2  = (const float*)d_in[10];
    const float* mw1 = (const float*)d_in[11];
    const float* mb1 = (const float*)d_in[12];
    const float* mw2 = (const float*)d_in[13];
    const float* mb2 = (const float*)d_in[14];
    const float* mw3 = (const float*)d_in[15];
    const float* mb3 = (const float*)d_in[16];
    float* out = (float*)d_out;

    float *p_xw, *p_h, *p_xw2, *p_z, *p_u, *p_v;
    float *p_as, *p_ad, *p_as2, *p_ad2;
    cudaGetSymbolAddress((void**)&p_xw,  g_xw);
    cudaGetSymbolAddress((void**)&p_h,   g_h);
    cudaGetSymbolAddress((void**)&p_xw2, g_xw2);
    cudaGetSymbolAddress((void**)&p_z,   g_z);
    cudaGetSymbolAddress((void**)&p_u,   g_u);
    cudaGetSymbolAddress((void**)&p_v,   g_v);
    cudaGetSymbolAddress((void**)&p_as,  g_as);
    cudaGetSymbolAddress((void**)&p_ad,  g_ad);
    cudaGetSymbolAddress((void**)&p_as2, g_as2);
    cudaGetSymbolAddress((void**)&p_ad2, g_ad2);

    cudaFuncSetAttribute(k_mlp, cudaFuncAttributeMaxDynamicSharedMemorySize,
                         SMEM_MLP);

    const int eb  = (Ee + 255) / 256;
    const int nb  = (Nn + 255) / 256;
    const int gb  = (Nn + 63) / 64;
    const int ab  = (Nn + 7) / 8;
    const int sb  = (Nn + 1023) / 1024;

    // CSR build interleaved with layer-1 GEMM (sgemm1 independent of CSR;
    // position 4 keeps it under the harness's fixed ncu window).
    k_zero<<<nb, 256>>>();
    k_count<<<eb, 256>>>(ei);
    k_scan1<<<sb, 1024>>>();
    k_sgemm<4, true><<<gb, 256>>>(x, W1, nullptr, p_xw, Nn, as1, ad1, p_as, p_ad);
    k_scan2<<<1, 32>>>(sb);
    k_scan3<<<nb, 256>>>();
    k_fill<<<eb, 256>>>(ei);

    // Layer 1 aggregation
    k_agg1<<<ab, 256>>>(b1);

    // Layer 2 GAT
    k_sgemm<1, true><<<gb, 256>>>(p_h, W2, nullptr, p_xw2, Nn, as2, ad2, p_as2, p_ad2);
    k_agg2<<<ab, 256>>>(b2);

    // Pair MLP precompute: u = z@mw1[:128] + mb1 ; v = z@mw1[128:]
    k_sgemm<1, false><<<gb, 256>>>(p_z, mw1, mb1, p_u, Nn,
                                   nullptr, nullptr, nullptr, nullptr);
    k_sgemm<1, false><<<gb, 256>>>(p_z, mw1 + 128 * 128, nullptr, p_v, Nn,
                                   nullptr, nullptr, nullptr, nullptr);

    // Edge-pair MLP (persistent; mb2 folded into accumulator init)
    k_mlp<<<MLP_BLOCKS, 256, SMEM_MLP>>>(ep, mw2, mb2, mw3, mb3, out);
}

// round 14
// speedup vs baseline: 1.5723x; 1.5723x over previous
#include <cuda_runtime.h>
#include <math.h>

#define Nn 50000
#define Ee 800000
#define Pp 800000

typedef unsigned long long u64;

// ---------------- scratch (device globals; no allocations allowed) ----------
__device__ float g_xw [Nn * 128];
__device__ float g_as [Nn * 4];
__device__ float g_ad [Nn * 4];
__device__ float g_h  [Nn * 128];
__device__ float g_xw2[Nn * 128];
__device__ float g_as2[Nn];
__device__ float g_ad2[Nn];
__device__ float g_z  [Nn * 128];
__device__ float g_u  [Nn * 128];
__device__ float g_v  [Nn * 128];
// CSR scratch
__device__ int g_deg[Nn];
__device__ int g_off[Nn + 1];
__device__ int g_cur[Nn];
__device__ int g_blk[64];
__device__ int g_src[Ee];

// ---------------- helpers ----------------------------------------------------
__device__ __forceinline__ float lrelu(float x) { return x > 0.f ? x : 0.2f * x; }
__device__ __forceinline__ float elu1(float x)  { return x > 0.f ? x : __expf(x) - 1.f; }

__device__ __forceinline__ u64 pack2(float lo, float hi) {
    u64 r;
    asm("mov.b64 %0, {%1, %2};" : "=l"(r)
        : "r"(__float_as_uint(lo)), "r"(__float_as_uint(hi)));
    return r;
}
__device__ __forceinline__ u64 ffma2(u64 a, u64 b, u64 c) {
    u64 d;
    asm("fma.rn.f32x2 %0, %1, %2, %3;" : "=l"(d) : "l"(a), "l"(b), "l"(c));
    return d;
}
__device__ __forceinline__ void unpack2(u64 v, float& lo, float& hi) {
    unsigned int a, b;
    asm("mov.b64 {%0, %1}, %2;" : "=r"(a), "=r"(b) : "l"(v));
    lo = __uint_as_float(a); hi = __uint_as_float(b);
}

// ---------------- CSR build --------------------------------------------------
__global__ void k_zero() {
    int i = blockIdx.x * blockDim.x + threadIdx.x;
    if (i < Nn) g_deg[i] = 0;
}

__global__ void k_count(const int* __restrict__ ei) {
    int e = blockIdx.x * blockDim.x + threadIdx.x;
    if (e < Ee) atomicAdd(&g_deg[ei[Ee + e]], 1);
}

__global__ void __launch_bounds__(1024) k_scan1() {
    __shared__ int wsum[32];
    int tid = threadIdx.x, lane = tid & 31, w = tid >> 5;
    int i = blockIdx.x * 1024 + tid;
    int v = (i < Nn) ? g_deg[i] : 0;
    int x = v;
#pragma unroll
    for (int off = 1; off < 32; off <<= 1) {
        int t = __shfl_up_sync(0xffffffffu, x, off);
        if (lane >= off) x += t;
    }
    if (lane == 31) wsum[w] = x;
    __syncthreads();
    if (w == 0) {
        int s = wsum[lane];
        int y = s;
#pragma unroll
        for (int off = 1; off < 32; off <<= 1) {
            int t = __shfl_up_sync(0xffffffffu, y, off);
            if (lane >= off) y += t;
        }
        wsum[lane] = y - s;
    }
    __syncthreads();
    int excl = (x - v) + wsum[w];
    if (i < Nn) g_off[i] = excl;
    if (tid == 1023) g_blk[blockIdx.x] = excl + v;
}

__global__ void k_scan2(int nblk) {
    int lane = threadIdx.x;
    int carry = 0;
    for (int c = 0; c < 2; c++) {
        int i = c * 32 + lane;
        int v = (i < nblk) ? g_blk[i] : 0;
        int x = v;
#pragma unroll
        for (int off = 1; off < 32; off <<= 1) {
            int t = __shfl_up_sync(0xffffffffu, x, off);
            if (lane >= off) x += t;
        }
        if (i < nblk) g_blk[i] = carry + x - v;
        carry += __shfl_sync(0xffffffffu, x, 31);
    }
    if (lane == 0) g_off[Nn] = Ee;
}

__global__ void k_scan3() {
    int i = blockIdx.x * blockDim.x + threadIdx.x;
    if (i >= Nn) return;
    int o = g_off[i] + g_blk[i >> 10];
    g_off[i] = o;
    g_cur[i] = o;
}

__global__ void k_fill(const int* __restrict__ ei) {
    int e = blockIdx.x * blockDim.x + threadIdx.x;
    if (e >= Ee) return;
    int s = ei[e], d = ei[Ee + e];
    int pos = atomicAdd(&g_cur[d], 1);
    g_src[pos] = s;
}

// ---------------- SGEMM: C[M,128] = A[M,128] @ B[128,128] (+bias) -----------
// ALPHA: also emit alpha_s/alpha_d dots (per HEADS) from registers in epilogue.
template <int HEADS, bool ALPHA>
__global__ void __launch_bounds__(256) k_sgemm(const float* __restrict__ A,
                                               const float* __restrict__ B,
                                               const float* __restrict__ bias,
                                               float* __restrict__ C, int M,
                                               const float* __restrict__ aSrc,
                                               const float* __restrict__ aDst,
                                               float* __restrict__ oS,
                                               float* __restrict__ oD) {
    __shared__ float As[16][64];
    __shared__ float Bs[16][128];
    int tid = threadIdx.x;
    int tx = tid & 31, ty = tid >> 5;
    int m0 = blockIdx.x * 64;
    u64 acc[8][2];
#pragma unroll
    for (int i = 0; i < 8; i++) { acc[i][0] = 0ull; acc[i][1] = 0ull; }

    for (int kk = 0; kk < 128; kk += 16) {
        {
            int m = tid >> 2;
            int kq = tid & 3;
            float4 v = make_float4(0.f, 0.f, 0.f, 0.f);
            if (m0 + m < M)
                v = *(const float4*)(A + (size_t)(m0 + m) * 128 + kk + kq * 4);
            As[kq * 4 + 0][m] = v.x; As[kq * 4 + 1][m] = v.y;
            As[kq * 4 + 2][m] = v.z; As[kq * 4 + 3][m] = v.w;
        }
#pragma unroll
        for (int r = 0; r < 2; r++) {
            int idx = tid + r * 256;
            int k = idx >> 5, c4 = idx & 31;
            *(float4*)&Bs[k][c4 * 4] =
                *(const float4*)(B + (size_t)(kk + k) * 128 + c4 * 4);
        }
        __syncthreads();
#pragma unroll
        for (int k = 0; k < 16; k++) {
            float4 b = *(float4*)&Bs[k][tx * 4];
            u64 b01 = pack2(b.x, b.y), b23 = pack2(b.z, b.w);
#pragma unroll
            for (int i = 0; i < 8; i++) {
                float a = As[k][ty * 8 + i];
                u64 aa = pack2(a, a);
                acc[i][0] = ffma2(aa, b01, acc[i][0]);
                acc[i][1] = ffma2(aa, b23, acc[i][1]);
            }
        }
        __syncthreads();
    }
    float4 bb = make_float4(0.f, 0.f, 0.f, 0.f);
    if (bias) bb = *(const float4*)(bias + tx * 4);
    float4 sv = make_float4(0.f, 0.f, 0.f, 0.f);
    float4 dv = make_float4(0.f, 0.f, 0.f, 0.f);
    if (ALPHA) {
        sv = *(const float4*)(aSrc + tx * 4);
        dv = *(const float4*)(aDst + tx * 4);
    }
#pragma unroll
    for (int i = 0; i < 8; i++) {
        int m = m0 + ty * 8 + i;
        if (m < M) {
            float4 o;
            unpack2(acc[i][0], o.x, o.y);
            unpack2(acc[i][1], o.z, o.w);
            float4 w;
            w.x = o.x + bb.x; w.y = o.y + bb.y;
            w.z = o.z + bb.z; w.w = o.w + bb.w;
            *(float4*)(C + (size_t)m * 128 + tx * 4) = w;
            if (ALPHA) {
                float ps = o.x * sv.x + o.y * sv.y + o.z * sv.z + o.w * sv.w;
                float pd = o.x * dv.x + o.y * dv.y + o.z * dv.z + o.w * dv.w;
                if (HEADS == 4) {
#pragma unroll
                    for (int off = 4; off; off >>= 1) {
                        ps += __shfl_down_sync(0xffffffffu, ps, off, 8);
                        pd += __shfl_down_sync(0xffffffffu, pd, off, 8);
                    }
                    if ((tx & 7) == 0) {
                        oS[m * 4 + (tx >> 3)] = ps;
                        oD[m * 4 + (tx >> 3)] = pd;
                    }
                } else {
#pragma unroll
                    for (int off = 16; off; off >>= 1) {
                        ps += __shfl_down_sync(0xffffffffu, ps, off);
                        pd += __shfl_down_sync(0xffffffffu, pd, off);
                    }
                    if (tx == 0) { oS[m] = ps; oD[m] = pd; }
                }
            }
        }
    }
}

// ---------------- gather-based softmax aggregation (CSR) ---------------------
__global__ void k_agg1(const float* __restrict__ b1) {
    int t = blockIdx.x * blockDim.x + threadIdx.x;
    int node = t >> 5, lane = t & 31;
    if (node >= Nn) return;
    int h = lane >> 3;
    float adh = g_ad[node * 4 + h];
    float ex = __expf(lrelu(g_as[node * 4 + h] + adh));
    const float4* xw4 = (const float4*)g_xw;
    float4 v = xw4[(size_t)node * 32 + lane];
    float4 acc; acc.x = ex * v.x; acc.y = ex * v.y; acc.z = ex * v.z; acc.w = ex * v.w;
    float den = ex;
    int e = g_off[node], e1 = g_off[node + 1];
    for (; e + 2 <= e1; e += 2) {
        int s0 = g_src[e], s1 = g_src[e + 1];
        float l0 = g_as[s0 * 4 + h], l1 = g_as[s1 * 4 + h];
        float4 v0 = xw4[(size_t)s0 * 32 + lane];
        float4 v1 = xw4[(size_t)s1 * 32 + lane];
        float x0 = __expf(lrelu(l0 + adh)), x1 = __expf(lrelu(l1 + adh));
        acc.x += x0 * v0.x + x1 * v1.x; acc.y += x0 * v0.y + x1 * v1.y;
        acc.z += x0 * v0.z + x1 * v1.z; acc.w += x0 * v0.w + x1 * v1.w;
        den += x0 + x1;
    }
    if (e < e1) {
        int s0 = g_src[e];
        float x0 = __expf(lrelu(g_as[s0 * 4 + h] + adh));
        float4 v0 = xw4[(size_t)s0 * 32 + lane];
        acc.x += x0 * v0.x; acc.y += x0 * v0.y;
        acc.z += x0 * v0.z; acc.w += x0 * v0.w;
        den += x0;
    }
    float inv = 1.f / den;
    float4 b = ((const float4*)b1)[lane];
    float4 o;
    o.x = elu1(acc.x * inv + b.x); o.y = elu1(acc.y * inv + b.y);
    o.z = elu1(acc.z * inv + b.z); o.w = elu1(acc.w * inv + b.w);
    ((float4*)g_h)[(size_t)node * 32 + lane] = o;
}

__global__ void k_agg2(const float* __restrict__ b2) {
    int t = blockIdx.x * blockDim.x + threadIdx.x;
    int node = t >> 5, lane = t & 31;
    if (node >= Nn) return;
    float adh = g_ad2[node];
    float ex = __expf(lrelu(g_as2[node] + adh));
    const float4* xw4 = (const float4*)g_xw2;
    float4 v = xw4[(size_t)node * 32 + lane];
    float4 acc; acc.x = ex * v.x; acc.y = ex * v.y; acc.z = ex * v.z; acc.w = ex * v.w;
    float den = ex;
    int e = g_off[node], e1 = g_off[node + 1];
    for (; e + 2 <= e1; e += 2) {
        int s0 = g_src[e], s1 = g_src[e + 1];
        float l0 = g_as2[s0], l1 = g_as2[s1];
        float4 v0 = xw4[(size_t)s0 * 32 + lane];
        float4 v1 = xw4[(size_t)s1 * 32 + lane];
        float x0 = __expf(lrelu(l0 + adh)), x1 = __expf(lrelu(l1 + adh));
        acc.x += x0 * v0.x + x1 * v1.x; acc.y += x0 * v0.y + x1 * v1.y;
        acc.z += x0 * v0.z + x1 * v1.z; acc.w += x0 * v0.w + x1 * v1.w;
        den += x0 + x1;
    }
    if (e < e1) {
        int s0 = g_src[e];
        float x0 = __expf(lrelu(g_as2[s0] + adh));
        float4 v0 = xw4[(size_t)s0 * 32 + lane];
        acc.x += x0 * v0.x; acc.y += x0 * v0.y;
        acc.z += x0 * v0.z; acc.w += x0 * v0.w;
        den += x0;
    }
    float inv = 1.f / den;
    float4 b = ((const float4*)b2)[lane];
    float4 o;
    o.x = acc.x * inv + b.x; o.y = acc.y * inv + b.y;
    o.z = acc.z * inv + b.z; o.w = acc.w * inv + b.w;
    ((float4*)g_z)[(size_t)node * 32 + lane] = o;
}

// ---------------- edge-pair MLP: persistent register-tiled GEMM --------------
// MT=64 pairs per tile; weights staged in smem ONCE per block (persistent).
// Column-pair packing (R4/R6 config — the known-good configuration).
#define MT 64
#define TS_STRIDE 132
#define NTILES (Pp / MT)
#define MLP_BLOCKS 456
#define SMEM_MLP (MT * TS_STRIDE * 4 + 128 * 32 * 8)

__global__ void __launch_bounds__(256) k_mlp(const int* __restrict__ ep,
                                             const float* __restrict__ mw2,
                                             const float* __restrict__ mb2,
                                             const float* __restrict__ mw3,
                                             const float* __restrict__ mb3,
                                             float* __restrict__ out) {
    extern __shared__ char smem[];
    float* Ts = (float*)smem;                       // [MT][TS_STRIDE]
    u64* w2p = (u64*)(smem + MT * TS_STRIDE * 4);   // [128][32] col pairs

    int tid = threadIdx.x;
    int tx = tid & 31, ty = tid >> 5;

    // stage packed weights once: w2p[k*32+c] = {mw2[k][c], mw2[k][c+32]}
    for (int e = tid; e < 128 * 32; e += 256) {
        int k = e >> 5, c = e & 31;
        w2p[e] = pack2(mw2[k * 64 + c], mw2[k * 64 + c + 32]);
    }
    u64 binit = pack2(__ldg(mb2 + tx), __ldg(mb2 + tx + 32));
    float w30 = __ldg(mw3 + tx), w31 = __ldg(mw3 + tx + 32);
    float mb3v = __ldg(mb3);
    int pair = tid >> 2, q = tid & 3;
    const float4* Ts4 = (const float4*)Ts;  // row stride = 33 float4

    for (int tile = blockIdx.x; tile < NTILES; tile += gridDim.x) {
        int P0 = tile * MT;
        __syncthreads();  // previous tile's readers done
        {   // gather + relu: 4 threads per pair, 8 float4 each
            int i = ep[P0 + pair], j = ep[Pp + P0 + pair];
            const float4* ur = (const float4*)g_u + (size_t)i * 32 + q * 8;
            const float4* vr = (const float4*)g_v + (size_t)j * 32 + q * 8;
            float4* dst = (float4*)(Ts + pair * TS_STRIDE) + q * 8;
#pragma unroll
            for (int r = 0; r < 8; r++) {
                float4 a = ur[r], b = vr[r], t;
                t.x = fmaxf(a.x + b.x, 0.f); t.y = fmaxf(a.y + b.y, 0.f);
                t.z = fmaxf(a.z + b.z, 0.f); t.w = fmaxf(a.w + b.w, 0.f);
                dst[r] = t;
            }
        }
        __syncthreads();

        u64 acc[8];
#pragma unroll
        for (int i = 0; i < 8; i++) acc[i] = binit;

#pragma unroll 2
        for (int kq = 0; kq < 32; kq++) {
            u64 b0 = w2p[(kq * 4 + 0) * 32 + tx];
            u64 b1 = w2p[(kq * 4 + 1) * 32 + tx];
            u64 b2 = w2p[(kq * 4 + 2) * 32 + tx];
            u64 b3 = w2p[(kq * 4 + 3) * 32 + tx];
#pragma unroll
            for (int i = 0; i < 8; i++) {
                float4 a = Ts4[(ty * 8 + i) * 33 + kq];
                acc[i] = ffma2(pack2(a.x, a.x), b0, acc[i]);
                acc[i] = ffma2(pack2(a.y, a.y), b1, acc[i]);
                acc[i] = ffma2(pack2(a.z, a.z), b2, acc[i]);
                acc[i] = ffma2(pack2(a.w, a.w), b3, acc[i]);
            }
        }

#pragma unroll
        for (int i = 0; i < 8; i++) {
            float o0, o1; unpack2(acc[i], o0, o1);
            o0 = fmaxf(o0, 0.f); o1 = fmaxf(o1, 0.f);
            float pv = o0 * w30 + o1 * w31;
#pragma unroll
            for (int off = 16; off; off >>= 1)
                pv += __shfl_down_sync(0xffffffffu, pv, off);
            if (tx == 0)
                out[P0 + ty * 8 + i] = 1.f / (1.f + __expf(-(pv + mb3v)));
        }
    }
}

// ---------------- launch ------------------------------------------------------
extern "C" void kernel_launch(void* const* d_in, const int* in_sizes, int n_in,
                              void* d_out, int out_size) {
    const float* x   = (const float*)d_in[0];
    const int*   ei  = (const int*)  d_in[1];
    const int*   ep  = (const int*)  d_in[2];
    const float* W1  = (const float*)d_in[3];
    const float* as1 = (const float*)d_in[4];
    const float* ad1 = (const float*)d_in[5];
    const float* b1  = (const float*)d_in[6];
    const float* W2  = (const float*)d_in[7];
    const float* as2 = (const float*)d_in[8];
    const float* ad2 = (const float*)d_in[9];
    const float* b2  = (const float*)d_in[10];
    const float* mw1 = (const float*)d_in[11];
    const float* mb1 = (const float*)d_in[12];
    const float* mw2 = (const float*)d_in[13];
    const float* mb2 = (const float*)d_in[14];
    const float* mw3 = (const float*)d_in[15];
    const float* mb3 = (const float*)d_in[16];
    float* out = (float*)d_out;

    float *p_xw, *p_h, *p_xw2, *p_z, *p_u, *p_v;
    float *p_as, *p_ad, *p_as2, *p_ad2;
    cudaGetSymbolAddress((void**)&p_xw,  g_xw);
    cudaGetSymbolAddress((void**)&p_h,   g_h);
    cudaGetSymbolAddress((void**)&p_xw2, g_xw2);
    cudaGetSymbolAddress((void**)&p_z,   g_z);
    cudaGetSymbolAddress((void**)&p_u,   g_u);
    cudaGetSymbolAddress((void**)&p_v,   g_v);
    cudaGetSymbolAddress((void**)&p_as,  g_as);
    cudaGetSymbolAddress((void**)&p_ad,  g_ad);
    cudaGetSymbolAddress((void**)&p_as2, g_as2);
    cudaGetSymbolAddress((void**)&p_ad2, g_ad2);

    cudaFuncSetAttribute(k_mlp, cudaFuncAttributeMaxDynamicSharedMemorySize,
                         SMEM_MLP);

    const int eb  = (Ee + 255) / 256;
    const int nb  = (Nn + 255) / 256;
    const int gb  = (Nn + 63) / 64;
    const int ab  = (Nn + 7) / 8;
    const int sb  = (Nn + 1023) / 1024;

    // CSR build interleaved with layer-1 GEMM (sgemm1 independent of CSR;
    // position 4 keeps it under the harness's fixed ncu window).
    k_zero<<<nb, 256>>>();
    k_count<<<eb, 256>>>(ei);
    k_scan1<<<sb, 1024>>>();
    k_sgemm<4, true><<<gb, 256>>>(x, W1, nullptr, p_xw, Nn, as1, ad1, p_as, p_ad);
    k_scan2<<<1, 32>>>(sb);
    k_scan3<<<nb, 256>>>();
    k_fill<<<eb, 256>>>(ei);

    // Layer 1 aggregation
    k_agg1<<<ab, 256>>>(b1);

    // Layer 2 GAT
    k_sgemm<1, true><<<gb, 256>>>(p_h, W2, nullptr, p_xw2, Nn, as2, ad2, p_as2, p_ad2);
    k_agg2<<<ab, 256>>>(b2);

    // Pair MLP precompute: u = z@mw1[:128] + mb1 ; v = z@mw1[128:]
    k_sgemm<1, false><<<gb, 256>>>(p_z, mw1, mb1, p_u, Nn,
                                   nullptr, nullptr, nullptr, nullptr);
    k_sgemm<1, false><<<gb, 256>>>(p_z, mw1 + 128 * 128, nullptr, p_v, Nn,
                                   nullptr, nullptr, nullptr, nullptr);

    // Edge-pair MLP (persistent; mb2 folded into accumulator init)
    k_mlp<<<MLP_BLOCKS, 256, SMEM_MLP>>>(ep, mw2, mb2, mw3, mb3, out);
}

// round 15
// speedup vs baseline: 3.0710x; 1.9532x over previous
#include <cuda_runtime.h>
#include <cuda_fp16.h>
#include <math.h>

#define Nn 50000
#define Ee 800000
#define Pp 800000

typedef unsigned long long u64;
typedef unsigned int u32;

// ---------------- scratch (device globals; no allocations allowed) ----------
__device__ float g_xw [Nn * 128];
__device__ float g_as [Nn * 4];
__device__ float g_ad [Nn * 4];
__device__ float g_h  [Nn * 128];
__device__ float g_xw2[Nn * 128];
__device__ float g_as2[Nn];
__device__ float g_ad2[Nn];
__device__ float g_z  [Nn * 128];
__device__ __half g_u16[Nn * 128];
__device__ __half g_v16[Nn * 128];
// CSR scratch
__device__ int g_deg[Nn];
__device__ int g_off[Nn + 1];
__device__ int g_cur[Nn];
__device__ int g_blk[64];
__device__ int g_src[Ee];

// ---------------- helpers ----------------------------------------------------
__device__ __forceinline__ float lrelu(float x) { return x > 0.f ? x : 0.2f * x; }
__device__ __forceinline__ float elu1(float x)  { return x > 0.f ? x : __expf(x) - 1.f; }

__device__ __forceinline__ u64 pack2(float lo, float hi) {
    u64 r;
    asm("mov.b64 %0, {%1, %2};" : "=l"(r)
        : "r"(__float_as_uint(lo)), "r"(__float_as_uint(hi)));
    return r;
}
__device__ __forceinline__ u64 ffma2(u64 a, u64 b, u64 c) {
    u64 d;
    asm("fma.rn.f32x2 %0, %1, %2, %3;" : "=l"(d) : "l"(a), "l"(b), "l"(c));
    return d;
}
__device__ __forceinline__ void unpack2(u64 v, float& lo, float& hi) {
    u32 a, b;
    asm("mov.b64 {%0, %1}, %2;" : "=r"(a), "=r"(b) : "l"(v));
    lo = __uint_as_float(a); hi = __uint_as_float(b);
}
__device__ __forceinline__ u32 h2u(__half2 h) { return *(u32*)&h; }

// ---------------- CSR build --------------------------------------------------
__global__ void k_zero() {
    int i = blockIdx.x * blockDim.x + threadIdx.x;
    if (i < Nn) g_deg[i] = 0;
}

__global__ void k_count(const int* __restrict__ ei) {
    int e = blockIdx.x * blockDim.x + threadIdx.x;
    if (e < Ee) atomicAdd(&g_deg[ei[Ee + e]], 1);
}

__global__ void __launch_bounds__(1024) k_scan1() {
    __shared__ int wsum[32];
    int tid = threadIdx.x, lane = tid & 31, w = tid >> 5;
    int i = blockIdx.x * 1024 + tid;
    int v = (i < Nn) ? g_deg[i] : 0;
    int x = v;
#pragma unroll
    for (int off = 1; off < 32; off <<= 1) {
        int t = __shfl_up_sync(0xffffffffu, x, off);
        if (lane >= off) x += t;
    }
    if (lane == 31) wsum[w] = x;
    __syncthreads();
    if (w == 0) {
        int s = wsum[lane];
        int y = s;
#pragma unroll
        for (int off = 1; off < 32; off <<= 1) {
            int t = __shfl_up_sync(0xffffffffu, y, off);
            if (lane >= off) y += t;
        }
        wsum[lane] = y - s;
    }
    __syncthreads();
    int excl = (x - v) + wsum[w];
    if (i < Nn) g_off[i] = excl;
    if (tid == 1023) g_blk[blockIdx.x] = excl + v;
}

__global__ void k_scan2(int nblk) {
    int lane = threadIdx.x;
    int carry = 0;
    for (int c = 0; c < 2; c++) {
        int i = c * 32 + lane;
        int v = (i < nblk) ? g_blk[i] : 0;
        int x = v;
#pragma unroll
        for (int off = 1; off < 32; off <<= 1) {
            int t = __shfl_up_sync(0xffffffffu, x, off);
            if (lane >= off) x += t;
        }
        if (i < nblk) g_blk[i] = carry + x - v;
        carry += __shfl_sync(0xffffffffu, x, 31);
    }
    if (lane == 0) g_off[Nn] = Ee;
}

__global__ void k_scan3() {
    int i = blockIdx.x * blockDim.x + threadIdx.x;
    if (i >= Nn) return;
    int o = g_off[i] + g_blk[i >> 10];
    g_off[i] = o;
    g_cur[i] = o;
}

__global__ void k_fill(const int* __restrict__ ei) {
    int e = blockIdx.x * blockDim.x + threadIdx.x;
    if (e >= Ee) return;
    int s = ei[e], d = ei[Ee + e];
    int pos = atomicAdd(&g_cur[d], 1);
    g_src[pos] = s;
}

// ---------------- SGEMM: C[M,128] = A[M,128] @ B[128,128] (+bias) -----------
// ALPHA: also emit alpha_s/alpha_d dots (per HEADS) from registers in epilogue.
// HALFOUT: write fp16 output to Ch instead of fp32 to C (for u/v).
template <int HEADS, bool ALPHA, bool HALFOUT>
__global__ void __launch_bounds__(256) k_sgemm(const float* __restrict__ A,
                                               const float* __restrict__ B,
                                               const float* __restrict__ bias,
                                               float* __restrict__ C, int M,
                                               const float* __restrict__ aSrc,
                                               const float* __restrict__ aDst,
                                               float* __restrict__ oS,
                                               float* __restrict__ oD,
                                               __half* __restrict__ Ch) {
    __shared__ float As[16][64];
    __shared__ float Bs[16][128];
    int tid = threadIdx.x;
    int tx = tid & 31, ty = tid >> 5;
    int m0 = blockIdx.x * 64;
    u64 acc[8][2];
#pragma unroll
    for (int i = 0; i < 8; i++) { acc[i][0] = 0ull; acc[i][1] = 0ull; }

    for (int kk = 0; kk < 128; kk += 16) {
        {
            int m = tid >> 2;
            int kq = tid & 3;
            float4 v = make_float4(0.f, 0.f, 0.f, 0.f);
            if (m0 + m < M)
                v = *(const float4*)(A + (size_t)(m0 + m) * 128 + kk + kq * 4);
            As[kq * 4 + 0][m] = v.x; As[kq * 4 + 1][m] = v.y;
            As[kq * 4 + 2][m] = v.z; As[kq * 4 + 3][m] = v.w;
        }
#pragma unroll
        for (int r = 0; r < 2; r++) {
            int idx = tid + r * 256;
            int k = idx >> 5, c4 = idx & 31;
            *(float4*)&Bs[k][c4 * 4] =
                *(const float4*)(B + (size_t)(kk + k) * 128 + c4 * 4);
        }
        __syncthreads();
#pragma unroll
        for (int k = 0; k < 16; k++) {
            float4 b = *(float4*)&Bs[k][tx * 4];
            u64 b01 = pack2(b.x, b.y), b23 = pack2(b.z, b.w);
#pragma unroll
            for (int i = 0; i < 8; i++) {
                float a = As[k][ty * 8 + i];
                u64 aa = pack2(a, a);
                acc[i][0] = ffma2(aa, b01, acc[i][0]);
                acc[i][1] = ffma2(aa, b23, acc[i][1]);
            }
        }
        __syncthreads();
    }
    float4 bb = make_float4(0.f, 0.f, 0.f, 0.f);
    if (bias) bb = *(const float4*)(bias + tx * 4);
    float4 sv = make_float4(0.f, 0.f, 0.f, 0.f);
    float4 dv = make_float4(0.f, 0.f, 0.f, 0.f);
    if (ALPHA) {
        sv = *(const float4*)(aSrc + tx * 4);
        dv = *(const float4*)(aDst + tx * 4);
    }
#pragma unroll
    for (int i = 0; i < 8; i++) {
        int m = m0 + ty * 8 + i;
        if (m < M) {
            float4 o;
            unpack2(acc[i][0], o.x, o.y);
            unpack2(acc[i][1], o.z, o.w);
            float4 w;
            w.x = o.x + bb.x; w.y = o.y + bb.y;
            w.z = o.z + bb.z; w.w = o.w + bb.w;
            if (HALFOUT) {
                __half2 h0 = __floats2half2_rn(w.x, w.y);
                __half2 h1 = __floats2half2_rn(w.z, w.w);
                *(uint2*)(Ch + (size_t)m * 128 + tx * 4) =
                    make_uint2(h2u(h0), h2u(h1));
            } else {
                *(float4*)(C + (size_t)m * 128 + tx * 4) = w;
            }
            if (ALPHA) {
                float ps = o.x * sv.x + o.y * sv.y + o.z * sv.z + o.w * sv.w;
                float pd = o.x * dv.x + o.y * dv.y + o.z * dv.z + o.w * dv.w;
                if (HEADS == 4) {
#pragma unroll
                    for (int off = 4; off; off >>= 1) {
                        ps += __shfl_down_sync(0xffffffffu, ps, off, 8);
                        pd += __shfl_down_sync(0xffffffffu, pd, off, 8);
                    }
                    if ((tx & 7) == 0) {
                        oS[m * 4 + (tx >> 3)] = ps;
                        oD[m * 4 + (tx >> 3)] = pd;
                    }
                } else {
#pragma unroll
                    for (int off = 16; off; off >>= 1) {
                        ps += __shfl_down_sync(0xffffffffu, ps, off);
                        pd += __shfl_down_sync(0xffffffffu, pd, off);
                    }
                    if (tx == 0) { oS[m] = ps; oD[m] = pd; }
                }
            }
        }
    }
}

// ---------------- gather-based softmax aggregation (CSR) ---------------------
__global__ void k_agg1(const float* __restrict__ b1) {
    int t = blockIdx.x * blockDim.x + threadIdx.x;
    int node = t >> 5, lane = t & 31;
    if (node >= Nn) return;
    int h = lane >> 3;
    float adh = g_ad[node * 4 + h];
    float ex = __expf(lrelu(g_as[node * 4 + h] + adh));
    const float4* xw4 = (const float4*)g_xw;
    float4 v = xw4[(size_t)node * 32 + lane];
    float4 acc; acc.x = ex * v.x; acc.y = ex * v.y; acc.z = ex * v.z; acc.w = ex * v.w;
    float den = ex;
    int e = g_off[node], e1 = g_off[node + 1];
    for (; e + 2 <= e1; e += 2) {
        int s0 = g_src[e], s1 = g_src[e + 1];
        float l0 = g_as[s0 * 4 + h], l1 = g_as[s1 * 4 + h];
        float4 v0 = xw4[(size_t)s0 * 32 + lane];
        float4 v1 = xw4[(size_t)s1 * 32 + lane];
        float x0 = __expf(lrelu(l0 + adh)), x1 = __expf(lrelu(l1 + adh));
        acc.x += x0 * v0.x + x1 * v1.x; acc.y += x0 * v0.y + x1 * v1.y;
        acc.z += x0 * v0.z + x1 * v1.z; acc.w += x0 * v0.w + x1 * v1.w;
        den += x0 + x1;
    }
    if (e < e1) {
        int s0 = g_src[e];
        float x0 = __expf(lrelu(g_as[s0 * 4 + h] + adh));
        float4 v0 = xw4[(size_t)s0 * 32 + lane];
        acc.x += x0 * v0.x; acc.y += x0 * v0.y;
        acc.z += x0 * v0.z; acc.w += x0 * v0.w;
        den += x0;
    }
    float inv = 1.f / den;
    float4 b = ((const float4*)b1)[lane];
    float4 o;
    o.x = elu1(acc.x * inv + b.x); o.y = elu1(acc.y * inv + b.y);
    o.z = elu1(acc.z * inv + b.z); o.w = elu1(acc.w * inv + b.w);
    ((float4*)g_h)[(size_t)node * 32 + lane] = o;
}

__global__ void k_agg2(const float* __restrict__ b2) {
    int t = blockIdx.x * blockDim.x + threadIdx.x;
    int node = t >> 5, lane = t & 31;
    if (node >= Nn) return;
    float adh = g_ad2[node];
    float ex = __expf(lrelu(g_as2[node] + adh));
    const float4* xw4 = (const float4*)g_xw2;
    float4 v = xw4[(size_t)node * 32 + lane];
    float4 acc; acc.x = ex * v.x; acc.y = ex * v.y; acc.z = ex * v.z; acc.w = ex * v.w;
    float den = ex;
    int e = g_off[node], e1 = g_off[node + 1];
    for (; e + 2 <= e1; e += 2) {
        int s0 = g_src[e], s1 = g_src[e + 1];
        float l0 = g_as2[s0], l1 = g_as2[s1];
        float4 v0 = xw4[(size_t)s0 * 32 + lane];
        float4 v1 = xw4[(size_t)s1 * 32 + lane];
        float x0 = __expf(lrelu(l0 + adh)), x1 = __expf(lrelu(l1 + adh));
        acc.x += x0 * v0.x + x1 * v1.x; acc.y += x0 * v0.y + x1 * v1.y;
        acc.z += x0 * v0.z + x1 * v1.z; acc.w += x0 * v0.w + x1 * v1.w;
        den += x0 + x1;
    }
    if (e < e1) {
        int s0 = g_src[e];
        float x0 = __expf(lrelu(g_as2[s0] + adh));
        float4 v0 = xw4[(size_t)s0 * 32 + lane];
        acc.x += x0 * v0.x; acc.y += x0 * v0.y;
        acc.z += x0 * v0.z; acc.w += x0 * v0.w;
        den += x0;
    }
    float inv = 1.f / den;
    float4 b = ((const float4*)b2)[lane];
    float4 o;
    o.x = acc.x * inv + b.x; o.y = acc.y * inv + b.y;
    o.z = acc.z * inv + b.z; o.w = acc.w * inv + b.w;
    ((float4*)g_z)[(size_t)node * 32 + lane] = o;
}

// ---------------- edge-pair MLP: fp16 tensor-core GEMM (mma.sync) ------------
// Persistent. Per tile: 128 pairs. T[128][136] fp16 = relu(u16[i]+v16[j]).
// Each warp owns 8 output cols (n0=warp*8), computes all 128 rows via
// m16n8k16 HMMA (B fragments preloaded in registers from mw2), applies
// relu + mw3 dot, lane-reduces, writes per-warp partials; final 128-thread
// reduction does sigmoid.
#define MTC 128
#define TROW 136           // fp16 per row (8-half pad -> conflict-free frags)
#define NT_TC (Pp / MTC)   // 6250
#define MLPB 444

__global__ void __launch_bounds__(256, 3) k_mlp(const int* __restrict__ ep,
                                                const float* __restrict__ mw2,
                                                const float* __restrict__ mb2,
                                                const float* __restrict__ mw3,
                                                const float* __restrict__ mb3,
                                                float* __restrict__ out) {
    __shared__ __align__(16) __half T[MTC * TROW];
    __shared__ float part[8][128];

    int tid = threadIdx.x;
    int warp = tid >> 5, l = tid & 31;
    int n0 = warp * 8;
    int grp = l >> 2;              // 0..7 (row group)
    int qp  = (l & 3) * 2;         // col pair base within fragment

    // Preload B fragments (mw2 -> fp16 regs): b[ks][0]=k rows qp,qp+1;
    // b[ks][1]=k rows qp+8,qp+9; col = n0 + grp.
    u32 bf[8][2];
    {
        int bn = n0 + grp;
#pragma unroll
        for (int ks = 0; ks < 8; ks++) {
            int k0 = ks * 16 + qp;
            bf[ks][0] = h2u(__floats2half2_rn(mw2[(k0 + 0) * 64 + bn],
                                              mw2[(k0 + 1) * 64 + bn]));
            bf[ks][1] = h2u(__floats2half2_rn(mw2[(k0 + 8) * 64 + bn],
                                              mw2[(k0 + 9) * 64 + bn]));
        }
    }
    int ccol = n0 + qp;
    float cb0 = __ldg(mb2 + ccol), cb1 = __ldg(mb2 + ccol + 1);
    float w30 = __ldg(mw3 + ccol), w31 = __ldg(mw3 + ccol + 1);
    float mb3v = __ldg(mb3);

    int p = tid >> 1, phalf = tid & 1;
    const __half2 hz = __float2half2_rn(0.f);

    for (int tile = blockIdx.x; tile < NT_TC; tile += gridDim.x) {
        int P0 = tile * MTC;
        __syncthreads();  // prev tile's T/part readers done
        {   // gather + relu in fp16: 2 threads/pair, 128B each
            int i = ep[P0 + p], j = ep[Pp + P0 + p];
            const uint4* ur = (const uint4*)g_u16 + (size_t)i * 16 + phalf * 8;
            const uint4* vr = (const uint4*)g_v16 + (size_t)j * 16 + phalf * 8;
            uint4* dst = (uint4*)((char*)T + p * (TROW * 2) + phalf * 128);
#pragma unroll
            for (int r = 0; r < 8; r++) {
                uint4 a = ur[r], b = vr[r], o;
                o.x = h2u(__hmax2(__hadd2(*(__half2*)&a.x, *(__half2*)&b.x), hz));
                o.y = h2u(__hmax2(__hadd2(*(__half2*)&a.y, *(__half2*)&b.y), hz));
                o.z = h2u(__hmax2(__hadd2(*(__half2*)&a.z, *(__half2*)&b.z), hz));
                o.w = h2u(__hmax2(__hadd2(*(__half2*)&a.w, *(__half2*)&b.w), hz));
                dst[r] = o;
            }
        }
        __syncthreads();

#pragma unroll 2
        for (int slab = 0; slab < 8; slab++) {
            int m0 = slab * 16;
            float c0 = cb0, c1 = cb1, c2 = cb0, c3 = cb1;
            const __half* r0 = T + (m0 + grp) * TROW;
            const __half* r1 = T + (m0 + grp + 8) * TROW;
#pragma unroll
            for (int ks = 0; ks < 8; ks++) {
                int kk = ks * 16 + qp;
                u32 a0 = *(const u32*)(r0 + kk);
                u32 a1 = *(const u32*)(r1 + kk);
                u32 a2 = *(const u32*)(r0 + kk + 8);
                u32 a3 = *(const u32*)(r1 + kk + 8);
                asm volatile(
                    "mma.sync.aligned.m16n8k16.row.col.f32.f16.f16.f32 "
                    "{%0,%1,%2,%3}, {%4,%5,%6,%7}, {%8,%9}, {%0,%1,%2,%3};"
                    : "+f"(c0), "+f"(c1), "+f"(c2), "+f"(c3)
                    : "r"(a0), "r"(a1), "r"(a2), "r"(a3),
                      "r"(bf[ks][0]), "r"(bf[ks][1]));
            }
            float pv0 = fmaxf(c0, 0.f) * w30 + fmaxf(c1, 0.f) * w31;
            float pv1 = fmaxf(c2, 0.f) * w30 + fmaxf(c3, 0.f) * w31;
            pv0 += __shfl_xor_sync(0xffffffffu, pv0, 1);
            pv0 += __shfl_xor_sync(0xffffffffu, pv0, 2);
            pv1 += __shfl_xor_sync(0xffffffffu, pv1, 1);
            pv1 += __shfl_xor_sync(0xffffffffu, pv1, 2);
            if ((l & 3) == 0) {
                part[warp][m0 + grp]     = pv0;
                part[warp][m0 + grp + 8] = pv1;
            }
        }
        __syncthreads();

        if (tid < 128) {
            float s = mb3v;
#pragma unroll
            for (int w = 0; w < 8; w++) s += part[w][tid];
            out[P0 + tid] = 1.f / (1.f + __expf(-s));
        }
    }
}

// ---------------- launch ------------------------------------------------------
extern "C" void kernel_launch(void* const* d_in, const int* in_sizes, int n_in,
                              void* d_out, int out_size) {
    const float* x   = (const float*)d_in[0];
    const int*   ei  = (const int*)  d_in[1];
    const int*   ep  = (const int*)  d_in[2];
    const float* W1  = (const float*)d_in[3];
    const float* as1 = (const float*)d_in[4];
    const float* ad1 = (const float*)d_in[5];
    const float* b1  = (const float*)d_in[6];
    const float* W2  = (const float*)d_in[7];
    const float* as2 = (const float*)d_in[8];
    const float* ad2 = (const float*)d_in[9];
    const float* b2  = (const float*)d_in[10];
    const float* mw1 = (const float*)d_in[11];
    const float* mb1 = (const float*)d_in[12];
    const float* mw2 = (const float*)d_in[13];
    const float* mb2 = (const float*)d_in[14];
    const float* mw3 = (const float*)d_in[15];
    const float* mb3 = (const float*)d_in[16];
    float* out = (float*)d_out;

    float *p_xw, *p_h, *p_xw2, *p_z;
    float *p_as, *p_ad, *p_as2, *p_ad2;
    __half *p_u16, *p_v16;
    cudaGetSymbolAddress((void**)&p_xw,  g_xw);
    cudaGetSymbolAddress((void**)&p_h,   g_h);
    cudaGetSymbolAddress((void**)&p_xw2, g_xw2);
    cudaGetSymbolAddress((void**)&p_z,   g_z);
    cudaGetSymbolAddress((void**)&p_u16, g_u16);
    cudaGetSymbolAddress((void**)&p_v16, g_v16);
    cudaGetSymbolAddress((void**)&p_as,  g_as);
    cudaGetSymbolAddress((void**)&p_ad,  g_ad);
    cudaGetSymbolAddress((void**)&p_as2, g_as2);
    cudaGetSymbolAddress((void**)&p_ad2, g_ad2);

    const int eb  = (Ee + 255) / 256;
    const int nb  = (Nn + 255) / 256;
    const int gb  = (Nn + 63) / 64;
    const int ab  = (Nn + 7) / 8;
    const int sb  = (Nn + 1023) / 1024;

    // CSR build interleaved with layer-1 GEMM (sgemm1 independent of CSR;
    // position 4 keeps it under the harness's fixed ncu window).
    k_zero<<<nb, 256>>>();
    k_count<<<eb, 256>>>(ei);
    k_scan1<<<sb, 1024>>>();
    k_sgemm<4, true, false><<<gb, 256>>>(x, W1, nullptr, p_xw, Nn,
                                         as1, ad1, p_as, p_ad, nullptr);
    k_scan2<<<1, 32>>>(sb);
    k_scan3<<<nb, 256>>>();
    k_fill<<<eb, 256>>>(ei);

    // Layer 1 aggregation
    k_agg1<<<ab, 256>>>(b1);

    // Layer 2 GAT
    k_sgemm<1, true, false><<<gb, 256>>>(p_h, W2, nullptr, p_xw2, Nn,
                                         as2, ad2, p_as2, p_ad2, nullptr);
    k_agg2<<<ab, 256>>>(b2);

    // Pair MLP precompute (fp16 outputs): u = z@mw1[:128]+mb1 ; v = z@mw1[128:]
    k_sgemm<1, false, true><<<gb, 256>>>(p_z, mw1, mb1, nullptr, Nn,
                                         nullptr, nullptr, nullptr, nullptr,
                                         p_u16);
    k_sgemm<1, false, true><<<gb, 256>>>(p_z, mw1 + 128 * 128, nullptr, nullptr,
                                         Nn, nullptr, nullptr, nullptr, nullptr,
                                         p_v16);

    // Edge-pair MLP (persistent tensor-core GEMM)
    k_mlp<<<MLPB, 256>>>(ep, mw2, mb2, mw3, mb3, out);
}

// round 16
// speedup vs baseline: 3.9630x; 1.2904x over previous
#include <cuda_runtime.h>
#include <cuda_fp16.h>
#include <math.h>

#define Nn 50000
#define Ee 800000
#define Pp 800000

typedef unsigned long long u64;
typedef unsigned int u32;

// ---------------- scratch (device globals; no allocations allowed) ----------
__device__ __half g_x16[Nn * 128];
__device__ float g_xw [Nn * 128];
__device__ float g_as [Nn * 4];
__device__ float g_ad [Nn * 4];
__device__ __half g_h16[Nn * 128];
__device__ float g_xw2[Nn * 128];
__device__ float g_as2[Nn];
__device__ float g_ad2[Nn];
__device__ __half g_z16[Nn * 128];
__device__ __half g_u16[Nn * 128];
__device__ __half g_v16[Nn * 128];
__device__ __half g_wt[4 * 128 * 128];   // w1t, w2t, mu_t, mv_t  ([n][k] fp16)
// CSR scratch
__device__ int g_deg[Nn];
__device__ int g_off[Nn + 1];
__device__ int g_cur[Nn];
__device__ int g_blk[64];
__device__ int g_src[Ee];

// ---------------- helpers ----------------------------------------------------
__device__ __forceinline__ float lrelu(float x) { return x > 0.f ? x : 0.2f * x; }
__device__ __forceinline__ float elu1(float x)  { return x > 0.f ? x : __expf(x) - 1.f; }
__device__ __forceinline__ u32 h2u(__half2 h) { return *(u32*)&h; }

// ---------------- conversions ------------------------------------------------
__global__ void k_x16(const float* __restrict__ x) {
    int i = blockIdx.x * 256 + threadIdx.x;
    if (i >= Nn * 32) return;
    float4 v = ((const float4*)x)[i];
    uint2 o;
    o.x = h2u(__floats2half2_rn(v.x, v.y));
    o.y = h2u(__floats2half2_rn(v.z, v.w));
    ((uint2*)g_x16)[i] = o;
}

__global__ void k_wt(const float* __restrict__ W1, const float* __restrict__ W2,
                     const float* __restrict__ mw1) {
    int i = blockIdx.x * 256 + threadIdx.x;
    if (i >= 4 * 16384) return;
    int m = i >> 14, r = i & 16383;
    int n = r >> 7, k = r & 127;
    float v;
    if (m == 0)      v = W1[k * 128 + n];
    else if (m == 1) v = W2[k * 128 + n];
    else if (m == 2) v = mw1[k * 128 + n];
    else             v = mw1[(128 + k) * 128 + n];
    g_wt[i] = __float2half_rn(v);
}

// ---------------- CSR build --------------------------------------------------
__global__ void k_zero() {
    int i = blockIdx.x * blockDim.x + threadIdx.x;
    if (i < Nn) g_deg[i] = 0;
}

__global__ void k_count(const int* __restrict__ ei) {
    int e = blockIdx.x * blockDim.x + threadIdx.x;
    if (e < Ee) atomicAdd(&g_deg[ei[Ee + e]], 1);
}

__global__ void __launch_bounds__(1024) k_scan1() {
    __shared__ int wsum[32];
    int tid = threadIdx.x, lane = tid & 31, w = tid >> 5;
    int i = blockIdx.x * 1024 + tid;
    int v = (i < Nn) ? g_deg[i] : 0;
    int x = v;
#pragma unroll
    for (int off = 1; off < 32; off <<= 1) {
        int t = __shfl_up_sync(0xffffffffu, x, off);
        if (lane >= off) x += t;
    }
    if (lane == 31) wsum[w] = x;
    __syncthreads();
    if (w == 0) {
        int s = wsum[lane];
        int y = s;
#pragma unroll
        for (int off = 1; off < 32; off <<= 1) {
            int t = __shfl_up_sync(0xffffffffu, y, off);
            if (lane >= off) y += t;
        }
        wsum[lane] = y - s;
    }
    __syncthreads();
    int excl = (x - v) + wsum[w];
    if (i < Nn) g_off[i] = excl;
    if (tid == 1023) g_blk[blockIdx.x] = excl + v;
}

__global__ void k_scan2(int nblk) {
    int lane = threadIdx.x;
    int carry = 0;
    for (int c = 0; c < 2; c++) {
        int i = c * 32 + lane;
        int v = (i < nblk) ? g_blk[i] : 0;
        int x = v;
#pragma unroll
        for (int off = 1; off < 32; off <<= 1) {
            int t = __shfl_up_sync(0xffffffffu, x, off);
            if (lane >= off) x += t;
        }
        if (i < nblk) g_blk[i] = carry + x - v;
        carry += __shfl_sync(0xffffffffu, x, 31);
    }
    if (lane == 0) g_off[Nn] = Ee;
}

__global__ void k_scan3() {
    int i = blockIdx.x * blockDim.x + threadIdx.x;
    if (i >= Nn) return;
    int o = g_off[i] + g_blk[i >> 10];
    g_off[i] = o;
    g_cur[i] = o;
}

__global__ void k_fill(const int* __restrict__ ei) {
    int e = blockIdx.x * blockDim.x + threadIdx.x;
    if (e >= Ee) return;
    int s = ei[e], d = ei[Ee + e];
    int pos = atomicAdd(&g_cur[d], 1);
    g_src[pos] = s;
}

// ---------------- fp16 tensor-core GEMM: C[M,128] = A16[M,128] @ Bt^T --------
// Bt is [n][k] fp16 (pre-transposed). Fragment mapping identical to k_mlp's
// verified layout. 64-row M tile, 8 warps x 16 cols. fp32 accum.
#define HG_SMEM (64 * 136 * 2 + 128 * 136 * 2)

template <bool HALFOUT>
__global__ void __launch_bounds__(256) k_hgemm(const __half* __restrict__ A16,
                                               const __half* __restrict__ Bt,
                                               const float* __restrict__ bias,
                                               float* __restrict__ C,
                                               __half* __restrict__ Ch, int M) {
    extern __shared__ __half sm[];
    __half* As = sm;               // [64][136]
    __half* Bs = sm + 64 * 136;    // [128][136]
    int tid = threadIdx.x;
    int m0 = blockIdx.x * 64;

#pragma unroll
    for (int r = 0; r < 4; r++) {          // A: 1024 uint4
        int idx = tid + r * 256;
        int row = idx >> 4, c8 = idx & 15;
        uint4 v = make_uint4(0u, 0u, 0u, 0u);
        if (m0 + row < M)
            v = *(const uint4*)(A16 + (size_t)(m0 + row) * 128 + c8 * 8);
        *(uint4*)(As + row * 136 + c8 * 8) = v;
    }
#pragma unroll
    for (int r = 0; r < 8; r++) {          // B: 2048 uint4
        int idx = tid + r * 256;
        int row = idx >> 4, c8 = idx & 15;
        *(uint4*)(Bs + row * 136 + c8 * 8) =
            *(const uint4*)(Bt + (size_t)row * 128 + c8 * 8);
    }
    __syncthreads();

    int warp = tid >> 5, l = tid & 31;
    int n0 = warp * 16;
    int grp = l >> 2, qp = (l & 3) * 2;

    float acc[4][2][4];
#pragma unroll
    for (int mt = 0; mt < 4; mt++)
#pragma unroll
        for (int nt = 0; nt < 2; nt++)
#pragma unroll
            for (int c = 0; c < 4; c++) acc[mt][nt][c] = 0.f;

#pragma unroll
    for (int ks = 0; ks < 8; ks++) {
        int kk = ks * 16 + qp;
        const __half* bp0 = Bs + (n0 + grp) * 136;
        const __half* bp1 = Bs + (n0 + 8 + grp) * 136;
        u32 b00 = *(const u32*)(bp0 + kk);
        u32 b01 = *(const u32*)(bp0 + kk + 8);
        u32 b10 = *(const u32*)(bp1 + kk);
        u32 b11 = *(const u32*)(bp1 + kk + 8);
#pragma unroll
        for (int mt = 0; mt < 4; mt++) {
            const __half* r0 = As + (mt * 16 + grp) * 136;
            const __half* r1 = As + (mt * 16 + 8 + grp) * 136;
            u32 a0 = *(const u32*)(r0 + kk);
            u32 a1 = *(const u32*)(r1 + kk);
            u32 a2 = *(const u32*)(r0 + kk + 8);
            u32 a3 = *(const u32*)(r1 + kk + 8);
            asm volatile(
                "mma.sync.aligned.m16n8k16.row.col.f32.f16.f16.f32 "
                "{%0,%1,%2,%3}, {%4,%5,%6,%7}, {%8,%9}, {%0,%1,%2,%3};"
                : "+f"(acc[mt][0][0]), "+f"(acc[mt][0][1]),
                  "+f"(acc[mt][0][2]), "+f"(acc[mt][0][3])
                : "r"(a0), "r"(a1), "r"(a2), "r"(a3), "r"(b00), "r"(b01));
            asm volatile(
                "mma.sync.aligned.m16n8k16.row.col.f32.f16.f16.f32 "
                "{%0,%1,%2,%3}, {%4,%5,%6,%7}, {%8,%9}, {%0,%1,%2,%3};"
                : "+f"(acc[mt][1][0]), "+f"(acc[mt][1][1]),
                  "+f"(acc[mt][1][2]), "+f"(acc[mt][1][3])
                : "r"(a0), "r"(a1), "r"(a2), "r"(a3), "r"(b10), "r"(b11));
        }
    }

    float bv[2][2] = {{0.f, 0.f}, {0.f, 0.f}};
    if (bias) {
        bv[0][0] = bias[n0 + qp];     bv[0][1] = bias[n0 + qp + 1];
        bv[1][0] = bias[n0 + 8 + qp]; bv[1][1] = bias[n0 + 8 + qp + 1];
    }
#pragma unroll
    for (int mt = 0; mt < 4; mt++) {
        int row0 = m0 + mt * 16 + grp;
        int row1 = row0 + 8;
#pragma unroll
        for (int nt = 0; nt < 2; nt++) {
            int cn = n0 + nt * 8 + qp;
            float c0 = acc[mt][nt][0] + bv[nt][0];
            float c1 = acc[mt][nt][1] + bv[nt][1];
            float c2 = acc[mt][nt][2] + bv[nt][0];
            float c3 = acc[mt][nt][3] + bv[nt][1];
            if (HALFOUT) {
                if (row0 < M)
                    *(u32*)(Ch + (size_t)row0 * 128 + cn) =
                        h2u(__floats2half2_rn(c0, c1));
                if (row1 < M)
                    *(u32*)(Ch + (size_t)row1 * 128 + cn) =
                        h2u(__floats2half2_rn(c2, c3));
            } else {
                if (row0 < M)
                    *(float2*)(C + (size_t)row0 * 128 + cn) =
                        make_float2(c0, c1);
                if (row1 < M)
                    *(float2*)(C + (size_t)row1 * 128 + cn) =
                        make_float2(c2, c3);
            }
        }
    }
}

// ---------------- attention coefficient dots --------------------------------
__global__ void k_alpha4(const float* __restrict__ aS, const float* __restrict__ aD) {
    int t = blockIdx.x * blockDim.x + threadIdx.x;
    int i = t >> 5, lane = t & 31;
    if (i >= Nn) return;
    float4 xv = *(const float4*)(g_xw + (size_t)i * 128 + lane * 4);
    float4 sv = *(const float4*)(aS + lane * 4);
    float4 dv = *(const float4*)(aD + lane * 4);
    float ps = xv.x * sv.x + xv.y * sv.y + xv.z * sv.z + xv.w * sv.w;
    float pd = xv.x * dv.x + xv.y * dv.y + xv.z * dv.z + xv.w * dv.w;
#pragma unroll
    for (int off = 4; off; off >>= 1) {
        ps += __shfl_down_sync(0xffffffffu, ps, off, 8);
        pd += __shfl_down_sync(0xffffffffu, pd, off, 8);
    }
    if ((lane & 7) == 0) {
        int h = lane >> 3;
        g_as[i * 4 + h] = ps;
        g_ad[i * 4 + h] = pd;
    }
}

__global__ void k_alpha1(const float* __restrict__ aS, const float* __restrict__ aD) {
    int t = blockIdx.x * blockDim.x + threadIdx.x;
    int i = t >> 5, lane = t & 31;
    if (i >= Nn) return;
    float4 xv = *(const float4*)(g_xw2 + (size_t)i * 128 + lane * 4);
    float4 sv = *(const float4*)(aS + lane * 4);
    float4 dv = *(const float4*)(aD + lane * 4);
    float ps = xv.x * sv.x + xv.y * sv.y + xv.z * sv.z + xv.w * sv.w;
    float pd = xv.x * dv.x + xv.y * dv.y + xv.z * dv.z + xv.w * dv.w;
#pragma unroll
    for (int off = 16; off; off >>= 1) {
        ps += __shfl_down_sync(0xffffffffu, ps, off);
        pd += __shfl_down_sync(0xffffffffu, pd, off);
    }
    if (lane == 0) { g_as2[i] = ps; g_ad2[i] = pd; }
}

// ---------------- gather-based softmax aggregation (CSR) ---------------------
// Outputs fp16 directly (feeds the next fp16 GEMM).
__global__ void k_agg1(const float* __restrict__ b1) {
    int t = blockIdx.x * blockDim.x + threadIdx.x;
    int node = t >> 5, lane = t & 31;
    if (node >= Nn) return;
    int h = lane >> 3;
    float adh = g_ad[node * 4 + h];
    float ex = __expf(lrelu(g_as[node * 4 + h] + adh));
    const float4* xw4 = (const float4*)g_xw;
    float4 v = xw4[(size_t)node * 32 + lane];
    float4 acc; acc.x = ex * v.x; acc.y = ex * v.y; acc.z = ex * v.z; acc.w = ex * v.w;
    float den = ex;
    int e = g_off[node], e1 = g_off[node + 1];
    for (; e + 2 <= e1; e += 2) {
        int s0 = g_src[e], s1 = g_src[e + 1];
        float l0 = g_as[s0 * 4 + h], l1 = g_as[s1 * 4 + h];
        float4 v0 = xw4[(size_t)s0 * 32 + lane];
        float4 v1 = xw4[(size_t)s1 * 32 + lane];
        float x0 = __expf(lrelu(l0 + adh)), x1 = __expf(lrelu(l1 + adh));
        acc.x += x0 * v0.x + x1 * v1.x; acc.y += x0 * v0.y + x1 * v1.y;
        acc.z += x0 * v0.z + x1 * v1.z; acc.w += x0 * v0.w + x1 * v1.w;
        den += x0 + x1;
    }
    if (e < e1) {
        int s0 = g_src[e];
        float x0 = __expf(lrelu(g_as[s0 * 4 + h] + adh));
        float4 v0 = xw4[(size_t)s0 * 32 + lane];
        acc.x += x0 * v0.x; acc.y += x0 * v0.y;
        acc.z += x0 * v0.z; acc.w += x0 * v0.w;
        den += x0;
    }
    float inv = 1.f / den;
    float4 b = ((const float4*)b1)[lane];
    uint2 o;
    o.x = h2u(__floats2half2_rn(elu1(acc.x * inv + b.x), elu1(acc.y * inv + b.y)));
    o.y = h2u(__floats2half2_rn(elu1(acc.z * inv + b.z), elu1(acc.w * inv + b.w)));
    ((uint2*)g_h16)[(size_t)node * 32 + lane] = o;
}

__global__ void k_agg2(const float* __restrict__ b2) {
    int t = blockIdx.x * blockDim.x + threadIdx.x;
    int node = t >> 5, lane = t & 31;
    if (node >= Nn) return;
    float adh = g_ad2[node];
    float ex = __expf(lrelu(g_as2[node] + adh));
    const float4* xw4 = (const float4*)g_xw2;
    float4 v = xw4[(size_t)node * 32 + lane];
    float4 acc; acc.x = ex * v.x; acc.y = ex * v.y; acc.z = ex * v.z; acc.w = ex * v.w;
    float den = ex;
    int e = g_off[node], e1 = g_off[node + 1];
    for (; e + 2 <= e1; e += 2) {
        int s0 = g_src[e], s1 = g_src[e + 1];
        float l0 = g_as2[s0], l1 = g_as2[s1];
        float4 v0 = xw4[(size_t)s0 * 32 + lane];
        float4 v1 = xw4[(size_t)s1 * 32 + lane];
        float x0 = __expf(lrelu(l0 + adh)), x1 = __expf(lrelu(l1 + adh));
        acc.x += x0 * v0.x + x1 * v1.x; acc.y += x0 * v0.y + x1 * v1.y;
        acc.z += x0 * v0.z + x1 * v1.z; acc.w += x0 * v0.w + x1 * v1.w;
        den += x0 + x1;
    }
    if (e < e1) {
        int s0 = g_src[e];
        float x0 = __expf(lrelu(g_as2[s0] + adh));
        float4 v0 = xw4[(size_t)s0 * 32 + lane];
        acc.x += x0 * v0.x; acc.y += x0 * v0.y;
        acc.z += x0 * v0.z; acc.w += x0 * v0.w;
        den += x0;
    }
    float inv = 1.f / den;
    float4 b = ((const float4*)b2)[lane];
    uint2 o;
    o.x = h2u(__floats2half2_rn(acc.x * inv + b.x, acc.y * inv + b.y));
    o.y = h2u(__floats2half2_rn(acc.z * inv + b.z, acc.w * inv + b.w));
    ((uint2*)g_z16)[(size_t)node * 32 + lane] = o;
}

// ---------------- edge-pair MLP: fp16 tensor-core GEMM (unchanged R15) -------
#define MTC 128
#define TROW 136
#define NT_TC (Pp / MTC)
#define MLPB 444

__global__ void __launch_bounds__(256, 3) k_mlp(const int* __restrict__ ep,
                                                const float* __restrict__ mw2,
                                                const float* __restrict__ mb2,
                                                const float* __restrict__ mw3,
                                                const float* __restrict__ mb3,
                                                float* __restrict__ out) {
    __shared__ __align__(16) __half T[MTC * TROW];
    __shared__ float part[8][128];

    int tid = threadIdx.x;
    int warp = tid >> 5, l = tid & 31;
    int n0 = warp * 8;
    int grp = l >> 2;
    int qp  = (l & 3) * 2;

    u32 bf[8][2];
    {
        int bn = n0 + grp;
#pragma unroll
        for (int ks = 0; ks < 8; ks++) {
            int k0 = ks * 16 + qp;
            bf[ks][0] = h2u(__floats2half2_rn(mw2[(k0 + 0) * 64 + bn],
                                              mw2[(k0 + 1) * 64 + bn]));
            bf[ks][1] = h2u(__floats2half2_rn(mw2[(k0 + 8) * 64 + bn],
                                              mw2[(k0 + 9) * 64 + bn]));
        }
    }
    int ccol = n0 + qp;
    float cb0 = __ldg(mb2 + ccol), cb1 = __ldg(mb2 + ccol + 1);
    float w30 = __ldg(mw3 + ccol), w31 = __ldg(mw3 + ccol + 1);
    float mb3v = __ldg(mb3);

    int p = tid >> 1, phalf = tid & 1;
    const __half2 hz = __float2half2_rn(0.f);

    for (int tile = blockIdx.x; tile < NT_TC; tile += gridDim.x) {
        int P0 = tile * MTC;
        __syncthreads();
        {
            int i = ep[P0 + p], j = ep[Pp + P0 + p];
            const uint4* ur = (const uint4*)g_u16 + (size_t)i * 16 + phalf * 8;
            const uint4* vr = (const uint4*)g_v16 + (size_t)j * 16 + phalf * 8;
            uint4* dst = (uint4*)((char*)T + p * (TROW * 2) + phalf * 128);
#pragma unroll
            for (int r = 0; r < 8; r++) {
                uint4 a = ur[r], b = vr[r], o;
                o.x = h2u(__hmax2(__hadd2(*(__half2*)&a.x, *(__half2*)&b.x), hz));
                o.y = h2u(__hmax2(__hadd2(*(__half2*)&a.y, *(__half2*)&b.y), hz));
                o.z = h2u(__hmax2(__hadd2(*(__half2*)&a.z, *(__half2*)&b.z), hz));
                o.w = h2u(__hmax2(__hadd2(*(__half2*)&a.w, *(__half2*)&b.w), hz));
                dst[r] = o;
            }
        }
        __syncthreads();

#pragma unroll 2
        for (int slab = 0; slab < 8; slab++) {
            int m0 = slab * 16;
            float c0 = cb0, c1 = cb1, c2 = cb0, c3 = cb1;
            const __half* r0 = T + (m0 + grp) * TROW;
            const __half* r1 = T + (m0 + grp + 8) * TROW;
#pragma unroll
            for (int ks = 0; ks < 8; ks++) {
                int kk = ks * 16 + qp;
                u32 a0 = *(const u32*)(r0 + kk);
                u32 a1 = *(const u32*)(r1 + kk);
                u32 a2 = *(const u32*)(r0 + kk + 8);
                u32 a3 = *(const u32*)(r1 + kk + 8);
                asm volatile(
                    "mma.sync.aligned.m16n8k16.row.col.f32.f16.f16.f32 "
                    "{%0,%1,%2,%3}, {%4,%5,%6,%7}, {%8,%9}, {%0,%1,%2,%3};"
                    : "+f"(c0), "+f"(c1), "+f"(c2), "+f"(c3)
                    : "r"(a0), "r"(a1), "r"(a2), "r"(a3),
                      "r"(bf[ks][0]), "r"(bf[ks][1]));
            }
            float pv0 = fmaxf(c0, 0.f) * w30 + fmaxf(c1, 0.f) * w31;
            float pv1 = fmaxf(c2, 0.f) * w30 + fmaxf(c3, 0.f) * w31;
            pv0 += __shfl_xor_sync(0xffffffffu, pv0, 1);
            pv0 += __shfl_xor_sync(0xffffffffu, pv0, 2);
            pv1 += __shfl_xor_sync(0xffffffffu, pv1, 1);
            pv1 += __shfl_xor_sync(0xffffffffu, pv1, 2);
            if ((l & 3) == 0) {
                part[warp][m0 + grp]     = pv0;
                part[warp][m0 + grp + 8] = pv1;
            }
        }
        __syncthreads();

        if (tid < 128) {
            float s = mb3v;
#pragma unroll
            for (int w = 0; w < 8; w++) s += part[w][tid];
            out[P0 + tid] = 1.f / (1.f + __expf(-s));
        }
    }
}

// ---------------- launch ------------------------------------------------------
extern "C" void kernel_launch(void* const* d_in, const int* in_sizes, int n_in,
                              void* d_out, int out_size) {
    const float* x   = (const float*)d_in[0];
    const int*   ei  = (const int*)  d_in[1];
    const int*   ep  = (const int*)  d_in[2];
    const float* W1  = (const float*)d_in[3];
    const float* as1 = (const float*)d_in[4];
    const float* ad1 = (const float*)d_in[5];
    const float* b1  = (const float*)d_in[6];
    const float* W2  = (const float*)d_in[7];
    const float* as2 = (const float*)d_in[8];
    const float* ad2 = (const float*)d_in[9];
    const float* b2  = (const float*)d_in[10];
    const float* mw1 = (const float*)d_in[11];
    const float* mb1 = (const float*)d_in[12];
    const float* mw2 = (const float*)d_in[13];
    const float* mb2 = (const float*)d_in[14];
    const float* mw3 = (const float*)d_in[15];
    const float* mb3 = (const float*)d_in[16];
    float* out = (float*)d_out;

    float *p_xw, *p_xw2;
    __half *p_x16, *p_h16, *p_z16, *p_u16, *p_v16, *p_wt;
    cudaGetSymbolAddress((void**)&p_x16, g_x16);
    cudaGetSymbolAddress((void**)&p_xw,  g_xw);
    cudaGetSymbolAddress((void**)&p_xw2, g_xw2);
    cudaGetSymbolAddress((void**)&p_h16, g_h16);
    cudaGetSymbolAddress((void**)&p_z16, g_z16);
    cudaGetSymbolAddress((void**)&p_u16, g_u16);
    cudaGetSymbolAddress((void**)&p_v16, g_v16);
    cudaGetSymbolAddress((void**)&p_wt,  g_wt);

    cudaFuncSetAttribute(k_hgemm<false>,
                         cudaFuncAttributeMaxDynamicSharedMemorySize, HG_SMEM);
    cudaFuncSetAttribute(k_hgemm<true>,
                         cudaFuncAttributeMaxDynamicSharedMemorySize, HG_SMEM);

    const int eb  = (Ee + 255) / 256;
    const int nb  = (Nn + 255) / 256;
    const int gb  = (Nn + 63) / 64;
    const int ab  = (Nn + 7) / 8;
    const int sb  = (Nn + 1023) / 1024;

    // Conversions + CSR build + layer-1 GEMM (hgemm1 at launch slot 4 for ncu)
    k_x16<<<(Nn * 32 + 255) / 256, 256>>>(x);
    k_wt<<<(4 * 16384 + 255) / 256, 256>>>(W1, W2, mw1);
    k_zero<<<nb, 256>>>();
    k_hgemm<false><<<gb, 256, HG_SMEM>>>(p_x16, p_wt, nullptr, p_xw, nullptr, Nn);
    k_count<<<eb, 256>>>(ei);
    k_scan1<<<sb, 1024>>>();
    k_scan2<<<1, 32>>>(sb);
    k_scan3<<<nb, 256>>>();
    k_fill<<<eb, 256>>>(ei);

    // Layer 1 GAT
    k_alpha4<<<ab, 256>>>(as1, ad1);
    k_agg1<<<ab, 256>>>(b1);

    // Layer 2 GAT
    k_hgemm<false><<<gb, 256, HG_SMEM>>>(p_h16, p_wt + 16384, nullptr, p_xw2,
                                         nullptr, Nn);
    k_alpha1<<<ab, 256>>>(as2, ad2);
    k_agg2<<<ab, 256>>>(b2);

    // Pair MLP precompute: u = z@mw1[:128]+mb1 ; v = z@mw1[128:]
    k_hgemm<true><<<gb, 256, HG_SMEM>>>(p_z16, p_wt + 2 * 16384, mb1, nullptr,
                                        p_u16, Nn);
    k_hgemm<true><<<gb, 256, HG_SMEM>>>(p_z16, p_wt + 3 * 16384, nullptr, nullptr,
                                        p_v16, Nn);

    // Edge-pair MLP (persistent tensor-core GEMM)
    k_mlp<<<MLPB, 256>>>(ep, mw2, mb2, mw3, mb3, out);
}